// round 7
// baseline (speedup 1.0000x reference)
#include <cuda_runtime.h>
#include <cstdint>

// DIoU loss, HBM-bound streaming reduction (144 MB read, scalar out).
// R7: R6 single-launch kernel + __launch_bounds__(256, 6) to raise the reg
// cap to 42 so ptxas keeps all 12 front-batched loads live (R6's 32-reg
// allocation serialized them: occ 98% but DRAM fell to 67%).

#define EPS 1e-7f
#define UNROLL 4
#define THREADS 256
#define MAX_BLOCKS 8192

__device__ float g_partials[MAX_BLOCKS];
__device__ unsigned int g_ticket = 0;

__device__ __forceinline__ float diou_loss(float4 a, float4 b) {
    float area1 = (a.z - a.x) * (a.w - a.y);
    float area2 = (b.z - b.x) * (b.w - b.y);

    float ltx = fmaxf(a.x, b.x);
    float lty = fmaxf(a.y, b.y);
    float rbx = fminf(a.z, b.z);
    float rby = fminf(a.w, b.w);
    float iw = fmaxf(rbx - ltx, 0.0f);
    float ih = fmaxf(rby - lty, 0.0f);
    float inter = iw * ih;
    float uni = area1 + area2 - inter;

    float cltx = fminf(a.x, b.x);
    float clty = fminf(a.y, b.y);
    float crbx = fmaxf(a.z, b.z);
    float crby = fmaxf(a.w, b.w);
    float wc = crbx - cltx;
    float hc = crby - clty;
    float area_c = wc * hc;

    float iou = __fdividef(inter, uni);
    float giou = iou - __fdividef(area_c - uni, area_c);

    float dcx = (a.x + a.z) * 0.5f - (b.x + b.z) * 0.5f;
    float dcy = (a.y + a.w) * 0.5f - (b.y + b.w) * 0.5f;
    float d2 = dcx * dcx + dcy * dcy;
    float diag2 = wc * wc + hc * hc;
    float diou = giou - __fdividef(d2, diag2 + EPS);

    return 1.0f - diou;
}

__global__ void __launch_bounds__(THREADS, 6)
diou_kernel(const float4* __restrict__ boxes1,
            const float4* __restrict__ boxes2,
            const int* __restrict__ mask,
            const int* __restrict__ num_boxes,
            float* __restrict__ out,
            int N) {
    const int tile = THREADS * UNROLL;
    int base = blockIdx.x * tile + threadIdx.x;

    float acc = 0.0f;

    if (blockIdx.x * tile + tile <= N) {
        // Fast path: full tile, unconditional front-batched loads (MLP=12).
        float4 a[UNROLL], b[UNROLL];
        int m[UNROLL];
        #pragma unroll
        for (int j = 0; j < UNROLL; j++) {
            int i = base + j * THREADS;
            a[j] = __ldcs(&boxes1[i]);
            b[j] = __ldcs(&boxes2[i]);
            m[j] = __ldcs(&mask[i]);
        }
        #pragma unroll
        for (int j = 0; j < UNROLL; j++)
            acc += diou_loss(a[j], b[j]) * (float)(m[j] != 0);
    } else {
        // Tail tile (not taken for N = multiple of tile).
        #pragma unroll
        for (int j = 0; j < UNROLL; j++) {
            int i = base + j * THREADS;
            if (i < N) {
                float4 a = __ldcs(&boxes1[i]);
                float4 b = __ldcs(&boxes2[i]);
                int m = __ldcs(&mask[i]);
                acc += diou_loss(a, b) * (float)(m != 0);
            }
        }
    }

    // Block reduce.
    #pragma unroll
    for (int off = 16; off > 0; off >>= 1)
        acc += __shfl_down_sync(0xFFFFFFFFu, acc, off);

    __shared__ float warp_sums[THREADS / 32];
    __shared__ bool is_last;
    int lane = threadIdx.x & 31;
    int wid = threadIdx.x >> 5;
    if (lane == 0) warp_sums[wid] = acc;
    __syncthreads();

    if (wid == 0) {
        float v = (lane < THREADS / 32) ? warp_sums[lane] : 0.0f;
        #pragma unroll
        for (int off = 4; off > 0; off >>= 1)
            v += __shfl_down_sync(0xFFFFFFFFu, v, off);
        if (lane == 0) {
            g_partials[blockIdx.x] = v;
            __threadfence();
            unsigned int ticket = atomicAdd(&g_ticket, 1u);
            is_last = (ticket == gridDim.x - 1);
        }
    }
    __syncthreads();

    // Last block: reduce all partials, write out, reset ticket.
    if (is_last) {
        float v = 0.0f;
        for (int i = threadIdx.x; i < gridDim.x; i += THREADS)
            v += g_partials[i];
        #pragma unroll
        for (int off = 16; off > 0; off >>= 1)
            v += __shfl_down_sync(0xFFFFFFFFu, v, off);
        if (lane == 0) warp_sums[wid] = v;
        __syncthreads();
        if (wid == 0) {
            float s = (lane < THREADS / 32) ? warp_sums[lane] : 0.0f;
            #pragma unroll
            for (int off = 4; off > 0; off >>= 1)
                s += __shfl_down_sync(0xFFFFFFFFu, s, off);
            if (lane == 0) {
                g_ticket = 0;
                out[0] = s * (1.0f / (float)num_boxes[0]);
            }
        }
    }
}

extern "C" void kernel_launch(void* const* d_in, const int* in_sizes, int n_in,
                              void* d_out, int out_size) {
    const float4* boxes1 = (const float4*)d_in[0];
    const float4* boxes2 = (const float4*)d_in[1];
    const int* mask = (const int*)d_in[2];
    const int* num_boxes = (const int*)d_in[3];
    float* out = (float*)d_out;

    int N = in_sizes[0] / 4;  // B*Q elements

    int elems_per_block = THREADS * UNROLL;
    int blocks = (N + elems_per_block - 1) / elems_per_block;  // 4096
    if (blocks > MAX_BLOCKS) blocks = MAX_BLOCKS;               // (N fits)

    diou_kernel<<<blocks, THREADS>>>(boxes1, boxes2, mask, num_boxes, out, N);
}

// round 8
// speedup vs baseline: 1.2723x; 1.2723x over previous
#include <cuda_runtime.h>
#include <cstdint>

// DIoU loss, HBM-bound streaming reduction (144 MB read, scalar out).
// R8: R5 design (persistent CTAs + prefetch.global.L2 next tile + single
// launch finalize) — the best SCORED kernel (28.0us e2e; ncu-dur rankings
// were clock-state artifacts). One change: grid = 148*6 = 888 so all CTAs
// are resident in wave 1 (40 regs -> 6 CTAs/SM), removing the second-wave
// straggler tail that grid=1036 had.

#define EPS 1e-7f
#define UNROLL 4
#define THREADS 256
#define MAX_BLOCKS 4096

__device__ float g_partials[MAX_BLOCKS];
__device__ unsigned int g_ticket = 0;

__device__ __forceinline__ float diou_loss(float4 a, float4 b) {
    float area1 = (a.z - a.x) * (a.w - a.y);
    float area2 = (b.z - b.x) * (b.w - b.y);

    float ltx = fmaxf(a.x, b.x);
    float lty = fmaxf(a.y, b.y);
    float rbx = fminf(a.z, b.z);
    float rby = fminf(a.w, b.w);
    float iw = fmaxf(rbx - ltx, 0.0f);
    float ih = fmaxf(rby - lty, 0.0f);
    float inter = iw * ih;
    float uni = area1 + area2 - inter;

    float cltx = fminf(a.x, b.x);
    float clty = fminf(a.y, b.y);
    float crbx = fmaxf(a.z, b.z);
    float crby = fmaxf(a.w, b.w);
    float wc = crbx - cltx;
    float hc = crby - clty;
    float area_c = wc * hc;

    float iou = __fdividef(inter, uni);
    float giou = iou - __fdividef(area_c - uni, area_c);

    float dcx = (a.x + a.z) * 0.5f - (b.x + b.z) * 0.5f;
    float dcy = (a.y + a.w) * 0.5f - (b.y + b.w) * 0.5f;
    float d2 = dcx * dcx + dcy * dcy;
    float diag2 = wc * wc + hc * hc;
    float diou = giou - __fdividef(d2, diag2 + EPS);

    return 1.0f - diou;
}

__device__ __forceinline__ void prefetch_l2(const void* p) {
    asm volatile("prefetch.global.L2 [%0];" :: "l"(p));
}

__global__ void __launch_bounds__(THREADS)
diou_kernel(const float4* __restrict__ boxes1,
            const float4* __restrict__ boxes2,
            const int* __restrict__ mask,
            const int* __restrict__ num_boxes,
            float* __restrict__ out,
            int N, int numTiles) {
    const int tileElems = THREADS * UNROLL;
    float acc = 0.0f;

    for (int t = blockIdx.x; t < numTiles; t += gridDim.x) {
        int base = t * tileElems + threadIdx.x;

        if (t * tileElems + tileElems <= N) {
            // Fast path: front-batched unconditional loads (12 LDGs in flight).
            float4 a[UNROLL], b[UNROLL];
            int m[UNROLL];
            #pragma unroll
            for (int j = 0; j < UNROLL; j++) {
                int i = base + j * THREADS;
                a[j] = __ldcs(&boxes1[i]);
                b[j] = __ldcs(&boxes2[i]);
                m[j] = __ldcs(&mask[i]);
            }

            // Prefetch next tile into L2 while this tile's loads are in flight.
            int tn = t + gridDim.x;
            if (tn < numTiles) {
                int pb = tn * tileElems + threadIdx.x;
                #pragma unroll
                for (int j = 0; j < UNROLL; j++) {
                    prefetch_l2(&boxes1[pb + j * THREADS]);
                    prefetch_l2(&boxes2[pb + j * THREADS]);
                    prefetch_l2(&mask[pb + j * THREADS]);
                }
            }

            #pragma unroll
            for (int j = 0; j < UNROLL; j++)
                acc += diou_loss(a[j], b[j]) * (float)(m[j] != 0);
        } else {
            // Tail tile.
            #pragma unroll
            for (int j = 0; j < UNROLL; j++) {
                int i = base + j * THREADS;
                if (i < N) {
                    float4 a = __ldcs(&boxes1[i]);
                    float4 b = __ldcs(&boxes2[i]);
                    int m = __ldcs(&mask[i]);
                    acc += diou_loss(a, b) * (float)(m != 0);
                }
            }
        }
    }

    // Block reduce.
    #pragma unroll
    for (int off = 16; off > 0; off >>= 1)
        acc += __shfl_down_sync(0xFFFFFFFFu, acc, off);

    __shared__ float warp_sums[THREADS / 32];
    __shared__ bool is_last;
    int lane = threadIdx.x & 31;
    int wid = threadIdx.x >> 5;
    if (lane == 0) warp_sums[wid] = acc;
    __syncthreads();

    if (wid == 0) {
        float v = (lane < THREADS / 32) ? warp_sums[lane] : 0.0f;
        #pragma unroll
        for (int off = 4; off > 0; off >>= 1)
            v += __shfl_down_sync(0xFFFFFFFFu, v, off);
        if (lane == 0) {
            g_partials[blockIdx.x] = v;
            __threadfence();
            unsigned int ticket = atomicAdd(&g_ticket, 1u);
            is_last = (ticket == gridDim.x - 1);
        }
    }
    __syncthreads();

    // Last block: reduce all partials, write out, reset ticket.
    if (is_last) {
        float v = 0.0f;
        for (int i = threadIdx.x; i < gridDim.x; i += THREADS)
            v += g_partials[i];
        #pragma unroll
        for (int off = 16; off > 0; off >>= 1)
            v += __shfl_down_sync(0xFFFFFFFFu, v, off);
        if (lane == 0) warp_sums[wid] = v;
        __syncthreads();
        if (wid == 0) {
            float s = (lane < THREADS / 32) ? warp_sums[lane] : 0.0f;
            #pragma unroll
            for (int off = 4; off > 0; off >>= 1)
                s += __shfl_down_sync(0xFFFFFFFFu, s, off);
            if (lane == 0) {
                g_ticket = 0;
                out[0] = s * (1.0f / (float)num_boxes[0]);
            }
        }
    }
}

extern "C" void kernel_launch(void* const* d_in, const int* in_sizes, int n_in,
                              void* d_out, int out_size) {
    const float4* boxes1 = (const float4*)d_in[0];
    const float4* boxes2 = (const float4*)d_in[1];
    const int* mask = (const int*)d_in[2];
    const int* num_boxes = (const int*)d_in[3];
    float* out = (float*)d_out;

    int N = in_sizes[0] / 4;  // B*Q elements
    const int tileElems = THREADS * UNROLL;
    int numTiles = (N + tileElems - 1) / tileElems;  // 4096

    // Single fully-resident wave: 6 CTAs/SM at 40 regs, 148 SMs.
    int blocks = 148 * 6;
    if (blocks > numTiles) blocks = numTiles;
    if (blocks > MAX_BLOCKS) blocks = MAX_BLOCKS;

    diou_kernel<<<blocks, THREADS>>>(boxes1, boxes2, mask, num_boxes, out,
                                     N, numTiles);
}